// round 13
// baseline (speedup 1.0000x reference)
#include <cuda_runtime.h>

// Problem constants (match reference)
#define KK   16
#define YY   32
#define CC   16
#define SEGS (KK * YY)          // 512 composite bins
#define BINS (SEGS * CC)        // 8192 fp32 accumulators per replica
#define REPL 32                 // replicated scratch copies (per-warp assignment)
#define EPSV 1e-8f

// Scratch: 32 * 8192 * 4B = 1 MB. Zero at module load; finalize restores it
// to zero every call (replay-safe).
// Layout within a replica: [seg][sub] — a quad's 4 RED.128s write one
// CONTIGUOUS 64B segment row (load-bearing: keeps L1tex wavefronts per
// RED.E.128 low; both scatter variants tried cost +55us). Do not change.
__device__ float g_scratch[REPL * BINS];

// ---------------------------------------------------------------------------
// Kernel 1: streaming scatter-accumulate — proven quad-lane scheme.
// Proven geometry (R8, 72.2us, reproduced 3x): 1184 CTAs x 256 thr =
// 148 SMs x 8 CTAs = 2048 thr/SM (occupancy is load-bearing: halving it
// cost +23us; block=1024 at same occupancy cost +38us; do not change).
// CHANGE vs R8: all 4 lanes of a quad load the labels themselves (same
// address -> coalesced broadcast, identical wavefront count) instead of
// sub==0 + __shfl_sync. Deletes 1 SHFL (26cyc, MIO pipe) per iteration
// and removes it from the RED-address dependency chain.
// ---------------------------------------------------------------------------
__global__ void __launch_bounds__(256)
accum_kernel(const int* __restrict__ x_labels,
             const int* __restrict__ y_labels,
             const float4* __restrict__ post,   // float4 view of [N,16]
             int nrows) {
    const int tid  = blockIdx.x * blockDim.x + threadIdx.x;
    const int lane = threadIdx.x & 31;
    const int sub  = lane & 3;                       // which float4 of the row

    // per-warp replica: consecutive warps hit different 32KB scratch regions
    float* replica = g_scratch + ((tid >> 5) & (REPL - 1)) * BINS;

    const int rowstride = (gridDim.x * blockDim.x) >> 2;

#pragma unroll 8
    for (int row = tid >> 2; row < nrows; row += rowstride) {
        // all 4 lanes of a quad read the same labels (sector broadcast)
        const int seg = __ldcs(x_labels + row) * YY + __ldcs(y_labels + row);

        float4 v = __ldcs(post + (size_t)row * 4 + sub);
        float4* dst = reinterpret_cast<float4*>(replica + seg * CC + sub * 4);
        atomicAdd(dst, v);   // sm_90+ vector atomic -> RED.E.128 (no return)
    }
}

// ---------------------------------------------------------------------------
// Kernel 2: fold replicas + RE-ZERO scratch + add eps + normalize over Y.
// (Proven R8 epilogue, unchanged.) Grid = 16 blocks (one per k), 1024 thr.
// ---------------------------------------------------------------------------
__global__ void finalize_kernel(float* __restrict__ out) {
    __shared__ float4 s_part[1024];      // [chunk(8)][bin4(128)]

    const int k    = blockIdx.x;         // 0..15
    const int t    = threadIdx.x;        // 0..1023
    const int bin4 = t & 127;            // which float4 of the k-slice
    const int rch  = t >> 7;             // replica chunk 0..7

    float4* base = reinterpret_cast<float4*>(g_scratch) + k * 128 + bin4;
    const float4 zero = make_float4(0.f, 0.f, 0.f, 0.f);

    float4 acc = zero;
#pragma unroll
    for (int r = 0; r < 4; r++) {
        float4* p = base + (rch * 4 + r) * (BINS / 4);   // stride 32KB
        float4 v = *p;
        *p = zero;                        // restore for next replay
        acc.x += v.x; acc.y += v.y; acc.z += v.z; acc.w += v.w;
    }
    s_part[rch * 128 + bin4] = acc;
    __syncthreads();

#pragma unroll
    for (int step = 4; step >= 1; step >>= 1) {
        if (rch < step) {
            float4 a = s_part[rch * 128 + bin4];
            float4 b = s_part[(rch + step) * 128 + bin4];
            a.x += b.x; a.y += b.y; a.z += b.z; a.w += b.w;
            s_part[rch * 128 + bin4] = a;
        }
        __syncthreads();
    }

    if (t < 128) {
        float4 num = s_part[bin4];
        num.x += EPSV; num.y += EPSV; num.z += EPSV; num.w += EPSV;
        s_part[bin4] = num;
    }
    __syncthreads();
    if (t < 128) {
        const int sub = bin4 & 3;        // float4 chunk within a segment
        float4 num = s_part[bin4];
        float4 den = make_float4(0.f, 0.f, 0.f, 0.f);
#pragma unroll
        for (int yy = 0; yy < YY; yy++) {
            float4 v = s_part[yy * 4 + sub];
            den.x += v.x; den.y += v.y; den.z += v.z; den.w += v.w;
        }
        float4 r;
        r.x = num.x / den.x; r.y = num.y / den.y;
        r.z = num.z / den.z; r.w = num.w / den.w;
        reinterpret_cast<float4*>(out)[k * 128 + bin4] = r;
    }
}

// ---------------------------------------------------------------------------
// Launch — two nodes.
// ---------------------------------------------------------------------------
extern "C" void kernel_launch(void* const* d_in, const int* in_sizes, int n_in,
                              void* d_out, int out_size) {
    const int*    x_labels = (const int*)d_in[0];
    const int*    y_labels = (const int*)d_in[1];
    const float4* post     = (const float4*)d_in[2];
    float*        out      = (float*)d_out;

    const int nrows = in_sizes[0];      // N = 4194304

    // 1184 CTAs x 256 threads = 148 SMs x 8 resident CTAs: single wave.
    accum_kernel<<<1184, 256>>>(x_labels, y_labels, post, nrows);

    finalize_kernel<<<KK, 1024>>>(out);
}

// round 14
// speedup vs baseline: 1.5118x; 1.5118x over previous
#include <cuda_runtime.h>

// Problem constants (match reference)
#define KK   16
#define YY   32
#define CC   16
#define SEGS (KK * YY)          // 512 composite bins
#define BINS (SEGS * CC)        // 8192 fp32 accumulators per replica
#define REPL 32                 // replicated scratch copies (per-warp assignment)
#define EPSV 1e-8f

// Scratch: 32 * 8192 * 4B = 1 MB. __device__ global => zero at module load.
// finalize_kernel restores it to zero every call, so each graph replay (and
// the initial correctness call) starts clean. No memset node needed.
//
// Layout within a replica: [seg][sub] — a quad's 4 RED.128s write one
// CONTIGUOUS 64B segment row. Load-bearing, like every other detail of the
// accum loop. Perturbation history (all measured):
//   - [sub][seg] transposed layout:      +55us (L1tex wavefronts x4)
//   - row-per-thread ownership:          +55us (same mechanism)
//   - all-lane label loads (no SHFL):    +37us (L1tex lane-requests x4)
//   - block=1024 same occupancy:         +38us
//   - occupancy halved (256,4):          +23us
//   - __ldcs, REPL 32/64/128, unroll 4/8, per-CTA vs per-warp replica: ~0
// DO NOT MODIFY the accum loop.
__device__ float g_scratch[REPL * BINS];

// ---------------------------------------------------------------------------
// Kernel 1: streaming scatter-accumulate — proven quad-lane scheme (~66us).
// 4 lanes cooperate on one row: lane sub==0 loads the labels, broadcasts seg
// via SHFL to its quad; each lane loads one float4 of the 16-channel row
// (warp reads 8 consecutive rows = 512 contiguous bytes, coalesced) and
// issues one no-return float4 global atomic (RED.E.128) into a contiguous
// 64B segment row of this warp's replica.
// Grid = 1184 CTAs x 256 thr = 148 SMs x 8 resident CTAs: single wave,
// 2048 thr/SM.
// ---------------------------------------------------------------------------
__global__ void __launch_bounds__(256)
accum_kernel(const int* __restrict__ x_labels,
             const int* __restrict__ y_labels,
             const float4* __restrict__ post,   // float4 view of [N,16]
             int nrows) {
    const int tid  = blockIdx.x * blockDim.x + threadIdx.x;
    const int lane = threadIdx.x & 31;
    const int sub  = lane & 3;                       // which float4 of the row

    // per-warp replica: consecutive warps hit different 32KB scratch regions
    float* replica = g_scratch + ((tid >> 5) & (REPL - 1)) * BINS;

    const int rowstride = (gridDim.x * blockDim.x) >> 2;

#pragma unroll 8
    for (int row = tid >> 2; row < nrows; row += rowstride) {
        int seg = 0;
        if (sub == 0) seg = __ldcs(x_labels + row) * YY + __ldcs(y_labels + row);
        seg = __shfl_sync(0xffffffffu, seg, lane & ~3);

        float4 v = __ldcs(post + (size_t)row * 4 + sub);
        float4* dst = reinterpret_cast<float4*>(replica + seg * CC + sub * 4);
        atomicAdd(dst, v);   // sm_90+ vector atomic -> RED.E.128 (no return)
    }
}

// ---------------------------------------------------------------------------
// Kernel 2: fold replicas + RE-ZERO scratch + add eps + normalize over Y.
// Grid = 16 blocks (one per k), 1024 threads.
//   Thread t: bin4 = t & 127, replica-chunk rch = t >> 7 (8 chunks of 4).
//   Each thread: 4 independent float4 loads, each followed by a zero store
//   to the same address (pure issue cost, off the reduce dependency chain).
//   Covers all 65536 scratch float4s exactly once.
// ---------------------------------------------------------------------------
__global__ void finalize_kernel(float* __restrict__ out) {
    __shared__ float4 s_part[1024];      // [chunk(8)][bin4(128)]

    const int k    = blockIdx.x;         // 0..15
    const int t    = threadIdx.x;        // 0..1023
    const int bin4 = t & 127;            // which float4 of the k-slice
    const int rch  = t >> 7;             // replica chunk 0..7

    float4* base = reinterpret_cast<float4*>(g_scratch) + k * 128 + bin4;
    const float4 zero = make_float4(0.f, 0.f, 0.f, 0.f);

    float4 acc = zero;
#pragma unroll
    for (int r = 0; r < 4; r++) {
        float4* p = base + (rch * 4 + r) * (BINS / 4);   // stride 32KB
        float4 v = *p;
        *p = zero;                        // restore for next replay
        acc.x += v.x; acc.y += v.y; acc.z += v.z; acc.w += v.w;
    }
    s_part[rch * 128 + bin4] = acc;
    __syncthreads();

#pragma unroll
    for (int step = 4; step >= 1; step >>= 1) {
        if (rch < step) {
            float4 a = s_part[rch * 128 + bin4];
            float4 b = s_part[(rch + step) * 128 + bin4];
            a.x += b.x; a.y += b.y; a.z += b.z; a.w += b.w;
            s_part[rch * 128 + bin4] = a;
        }
        __syncthreads();
    }

    if (t < 128) {
        float4 num = s_part[bin4];
        num.x += EPSV; num.y += EPSV; num.z += EPSV; num.w += EPSV;
        s_part[bin4] = num;
    }
    __syncthreads();
    if (t < 128) {
        const int sub = bin4 & 3;        // float4 chunk within a segment
        float4 num = s_part[bin4];
        float4 den = make_float4(0.f, 0.f, 0.f, 0.f);
#pragma unroll
        for (int yy = 0; yy < YY; yy++) {
            float4 v = s_part[yy * 4 + sub];
            den.x += v.x; den.y += v.y; den.z += v.z; den.w += v.w;
        }
        float4 r;
        r.x = num.x / den.x; r.y = num.y / den.y;
        r.z = num.z / den.z; r.w = num.w / den.w;
        reinterpret_cast<float4*>(out)[k * 128 + bin4] = r;
    }
}

// ---------------------------------------------------------------------------
// Launch — two nodes only.
// ---------------------------------------------------------------------------
extern "C" void kernel_launch(void* const* d_in, const int* in_sizes, int n_in,
                              void* d_out, int out_size) {
    const int*    x_labels = (const int*)d_in[0];
    const int*    y_labels = (const int*)d_in[1];
    const float4* post     = (const float4*)d_in[2];
    float*        out      = (float*)d_out;

    const int nrows = in_sizes[0];      // N = 4194304

    // 1184 CTAs x 256 threads = 148 SMs x 8 resident CTAs: single wave.
    accum_kernel<<<1184, 256>>>(x_labels, y_labels, post, nrows);

    finalize_kernel<<<KK, 1024>>>(out);
}